// round 3
// baseline (speedup 1.0000x reference)
#include <cuda_runtime.h>

// ChamferLoss: B=4, C=3, N=M=8192
// loss = 2/B * sum_{b,n} max( min_m ||q_bn - r_bm||^2 , 0 )

#define BATCH   4
#define NPTS    8192
#define TPB     256
#define QBLOCKS (NPTS / TPB)        // 32 query-blocks per batch
#define NBLOCKS (BATCH * QBLOCKS)   // 128 blocks total
#define SMEM_BYTES (NPTS * 16)      // 8192 float4 = 128 KB

__device__ float g_partial[NBLOCKS];

__global__ void __launch_bounds__(TPB, 1)
chamfer_min_kernel(const float* __restrict__ pc2,
                   const float* __restrict__ pc1w)
{
    extern __shared__ float4 sref[];   // [NPTS] : x, y, z, x^2+y^2+z^2

    const int b  = blockIdx.x / QBLOCKS;
    const int qb = blockIdx.x % QBLOCKS;

    // Stage all ref points of this batch into shared memory.
    const float* __restrict__ rp = pc1w + (size_t)b * 3 * NPTS;
    for (int m = threadIdx.x; m < NPTS; m += TPB) {
        float x = rp[m];
        float y = rp[NPTS + m];
        float z = rp[2 * NPTS + m];
        sref[m] = make_float4(x, y, z, fmaf(x, x, fmaf(y, y, z * z)));
    }
    __syncthreads();

    // One query point per thread, held in registers.
    const int n = qb * TPB + threadIdx.x;
    const float* __restrict__ qp = pc2 + (size_t)b * 3 * NPTS;
    const float qx = qp[n];
    const float qy = qp[NPTS + n];
    const float qz = qp[2 * NPTS + n];
    const float q2 = fmaf(qx, qx, fmaf(qy, qy, qz * qz));

    // Track min over t_m = r2 - 2*dot(q, r); true dist = q2 + t (clamped >= 0).
    float m0 = 3.4e38f, m1 = 3.4e38f, m2 = 3.4e38f, m3 = 3.4e38f;

    #pragma unroll 1
    for (int j = 0; j < NPTS; j += 4) {
        float4 r0 = sref[j + 0];
        float4 r1 = sref[j + 1];
        float4 r2 = sref[j + 2];
        float4 r3 = sref[j + 3];

        float t0 = fmaf(-2.0f, fmaf(qz, r0.z, fmaf(qy, r0.y, qx * r0.x)), r0.w);
        float t1 = fmaf(-2.0f, fmaf(qz, r1.z, fmaf(qy, r1.y, qx * r1.x)), r1.w);
        float t2 = fmaf(-2.0f, fmaf(qz, r2.z, fmaf(qy, r2.y, qx * r2.x)), r2.w);
        float t3 = fmaf(-2.0f, fmaf(qz, r3.z, fmaf(qy, r3.y, qx * r3.x)), r3.w);

        m0 = fminf(m0, t0);
        m1 = fminf(m1, t1);
        m2 = fminf(m2, t2);
        m3 = fminf(m3, t3);
    }

    float mn = fminf(fminf(m0, m1), fminf(m2, m3));
    float d  = fmaxf(q2 + mn, 0.0f);   // clamp commutes with min

    // Deterministic block-level sum reduction.
    __shared__ float red[TPB];
    red[threadIdx.x] = d;
    __syncthreads();
    #pragma unroll
    for (int s = TPB / 2; s > 0; s >>= 1) {
        if (threadIdx.x < s) red[threadIdx.x] += red[threadIdx.x + s];
        __syncthreads();
    }
    if (threadIdx.x == 0) g_partial[blockIdx.x] = red[0];
}

__global__ void chamfer_finalize_kernel(float* __restrict__ out)
{
    // Single block, NBLOCKS threads: deterministic fixed-order reduction.
    __shared__ float red[NBLOCKS];
    red[threadIdx.x] = g_partial[threadIdx.x];
    __syncthreads();
    #pragma unroll
    for (int s = NBLOCKS / 2; s > 0; s >>= 1) {
        if (threadIdx.x < s) red[threadIdx.x] += red[threadIdx.x + s];
        __syncthreads();
    }
    if (threadIdx.x == 0) {
        // loss = 2 * (total_sum / BATCH)
        out[0] = red[0] * (2.0f / (float)BATCH);
    }
}

extern "C" void kernel_launch(void* const* d_in, const int* in_sizes, int n_in,
                              void* d_out, int out_size)
{
    const float* pc2  = (const float*)d_in[0];
    const float* pc1w = (const float*)d_in[1];
    float* out = (float*)d_out;

    static bool attr_set = false;
    if (!attr_set) {
        cudaFuncSetAttribute(chamfer_min_kernel,
                             cudaFuncAttributeMaxDynamicSharedMemorySize,
                             SMEM_BYTES);
        attr_set = true;
    }

    chamfer_min_kernel<<<NBLOCKS, TPB, SMEM_BYTES>>>(pc2, pc1w);
    chamfer_finalize_kernel<<<1, NBLOCKS>>>(out);
}

// round 4
// speedup vs baseline: 1.3166x; 1.3166x over previous
#include <cuda_runtime.h>

// ChamferLoss: B=4, C=3, N=M=8192
// loss = 2/B * sum_{b,n} max( min_m ||q_bn - r_bm||^2 , 0 )
//
// Strategy:
//  - refs staged in smem as pairs, pre-scaled: (-2x0,-2x1,-2y0,-2y1) (-2z0,-2z1,w0,w1)
//  - t = w + qx*(-2x) + qy*(-2y) + qz*(-2z), true dist = q2 + t (clamp at end)
//  - packed fma.rn.f32x2: one FFMA2 handles 2 ref points
//  - 2 queries per thread: each LDS.128 feeds 2 query chains

#define BATCH   4
#define NPTS    8192
#define NPAIRS  (NPTS / 2)          // 4096 ref pairs
#define TPB     128
#define QPT     2                   // queries per thread
#define QPB     (TPB * QPT)         // 256 queries per block
#define QBLOCKS (NPTS / QPB)        // 32
#define NBLOCKS (BATCH * QBLOCKS)   // 128
#define SMEM_BYTES (NPAIRS * 32)    // 2 float4 per pair = 128 KB

__device__ float g_partial[NBLOCKS];

__device__ __forceinline__ unsigned long long pk2(float lo, float hi) {
    unsigned long long r;
    asm("mov.b64 %0, {%1, %2};" : "=l"(r) : "f"(lo), "f"(hi));
    return r;
}
__device__ __forceinline__ unsigned long long fma_f32x2(
    unsigned long long a, unsigned long long b, unsigned long long c) {
    unsigned long long d;
    asm("fma.rn.f32x2 %0, %1, %2, %3;" : "=l"(d) : "l"(a), "l"(b), "l"(c));
    return d;
}
__device__ __forceinline__ float2 upk2(unsigned long long v) {
    float2 r;
    asm("mov.b64 {%0, %1}, %2;" : "=f"(r.x), "=f"(r.y) : "l"(v));
    return r;
}

__global__ void __launch_bounds__(TPB, 1)
chamfer_min_kernel(const float* __restrict__ pc2,
                   const float* __restrict__ pc1w)
{
    extern __shared__ float4 s[];   // [2*NPAIRS]: s[2p]=(-2x0,-2x1,-2y0,-2y1), s[2p+1]=(-2z0,-2z1,w0,w1)

    const int b  = blockIdx.x / QBLOCKS;
    const int qb = blockIdx.x % QBLOCKS;

    // Stage all ref points of this batch, pre-scaled and pair-packed.
    const float* __restrict__ rp = pc1w + (size_t)b * 3 * NPTS;
    for (int p = threadIdx.x; p < NPAIRS; p += TPB) {
        float x0 = rp[2 * p],            x1 = rp[2 * p + 1];
        float y0 = rp[NPTS + 2 * p],     y1 = rp[NPTS + 2 * p + 1];
        float z0 = rp[2 * NPTS + 2 * p], z1 = rp[2 * NPTS + 2 * p + 1];
        float w0 = fmaf(x0, x0, fmaf(y0, y0, z0 * z0));
        float w1 = fmaf(x1, x1, fmaf(y1, y1, z1 * z1));
        s[2 * p]     = make_float4(-2.0f * x0, -2.0f * x1, -2.0f * y0, -2.0f * y1);
        s[2 * p + 1] = make_float4(-2.0f * z0, -2.0f * z1, w0, w1);
    }
    __syncthreads();

    // Two query points per thread.
    const int na = qb * QPB + threadIdx.x;
    const int nb = na + TPB;
    const float* __restrict__ qp = pc2 + (size_t)b * 3 * NPTS;
    const float qxa = qp[na], qya = qp[NPTS + na], qza = qp[2 * NPTS + na];
    const float qxb = qp[nb], qyb = qp[NPTS + nb], qzb = qp[2 * NPTS + nb];
    const float q2a = fmaf(qxa, qxa, fmaf(qya, qya, qza * qza));
    const float q2b = fmaf(qxb, qxb, fmaf(qyb, qyb, qzb * qzb));

    // Broadcast query coords into both f32x2 halves.
    const unsigned long long QXA = pk2(qxa, qxa), QYA = pk2(qya, qya), QZA = pk2(qza, qza);
    const unsigned long long QXB = pk2(qxb, qxb), QYB = pk2(qyb, qyb), QZB = pk2(qzb, qzb);

    float ma0 = 3.4e38f, ma1 = 3.4e38f;  // query a, halves 0/1
    float mb0 = 3.4e38f, mb1 = 3.4e38f;  // query b

    #pragma unroll 1
    for (int p = 0; p < NPAIRS; p += 4) {
        #pragma unroll
        for (int u = 0; u < 4; u++) {
            float4 A = s[2 * (p + u)];       // -2x0,-2x1,-2y0,-2y1
            float4 Bv = s[2 * (p + u) + 1];  // -2z0,-2z1, w0, w1

            unsigned long long X = pk2(A.x, A.y);
            unsigned long long Y = pk2(A.z, A.w);
            unsigned long long Z = pk2(Bv.x, Bv.y);
            unsigned long long W = pk2(Bv.z, Bv.w);

            unsigned long long ta = fma_f32x2(QXA, X, fma_f32x2(QYA, Y, fma_f32x2(QZA, Z, W)));
            unsigned long long tb = fma_f32x2(QXB, X, fma_f32x2(QYB, Y, fma_f32x2(QZB, Z, W)));

            float2 fa = upk2(ta);
            float2 fb = upk2(tb);
            ma0 = fminf(ma0, fa.x);
            ma1 = fminf(ma1, fa.y);
            mb0 = fminf(mb0, fb.x);
            mb1 = fminf(mb1, fb.y);
        }
    }

    float da = fmaxf(q2a + fminf(ma0, ma1), 0.0f);
    float db = fmaxf(q2b + fminf(mb0, mb1), 0.0f);

    // Deterministic block-level sum reduction.
    __shared__ float red[TPB];
    red[threadIdx.x] = da + db;
    __syncthreads();
    #pragma unroll
    for (int sH = TPB / 2; sH > 0; sH >>= 1) {
        if (threadIdx.x < sH) red[threadIdx.x] += red[threadIdx.x + sH];
        __syncthreads();
    }
    if (threadIdx.x == 0) g_partial[blockIdx.x] = red[0];
}

__global__ void chamfer_finalize_kernel(float* __restrict__ out)
{
    __shared__ float red[NBLOCKS];
    red[threadIdx.x] = g_partial[threadIdx.x];
    __syncthreads();
    #pragma unroll
    for (int sH = NBLOCKS / 2; sH > 0; sH >>= 1) {
        if (threadIdx.x < sH) red[threadIdx.x] += red[threadIdx.x + sH];
        __syncthreads();
    }
    if (threadIdx.x == 0) {
        out[0] = red[0] * (2.0f / (float)BATCH);  // 2 * mean over batches
    }
}

extern "C" void kernel_launch(void* const* d_in, const int* in_sizes, int n_in,
                              void* d_out, int out_size)
{
    const float* pc2  = (const float*)d_in[0];
    const float* pc1w = (const float*)d_in[1];
    float* out = (float*)d_out;

    cudaFuncSetAttribute(chamfer_min_kernel,
                         cudaFuncAttributeMaxDynamicSharedMemorySize,
                         SMEM_BYTES);

    chamfer_min_kernel<<<NBLOCKS, TPB, SMEM_BYTES>>>(pc2, pc1w);
    chamfer_finalize_kernel<<<1, NBLOCKS>>>(out);
}

// round 5
// speedup vs baseline: 1.7217x; 1.3077x over previous
#include <cuda_runtime.h>
#include <cstdint>

// ChamferLoss: B=4, C=3, N=M=8192
// loss = 2/B * sum_{b,n} max( min_m ||q_bn - r_bm||^2 , 0 )
//
// refs in smem as pairs, pre-scaled:
//   s[2p]   = (-2x0,-2x1,-2y0,-2y1)   -> ld.shared.v2.b64 gives X,Y packed
//   s[2p+1] = (-2z0,-2z1, w0, w1)     -> ld.shared.v2.b64 gives Z,W packed
// t = qx*X + qy*Y + qz*Z + W  via fma.rn.f32x2 (2 ref pts / instr)
// true dist = q2 + t, clamp at end. 2 queries per thread share each LDS.

#define BATCH   4
#define NPTS    8192
#define NPAIRS  (NPTS / 2)
#define TPB     128
#define QPT     2
#define QPB     (TPB * QPT)         // 256
#define QBLOCKS (NPTS / QPB)        // 32
#define NBLOCKS (BATCH * QBLOCKS)   // 128
#define SMEM_BYTES (NPAIRS * 32)    // 128 KB

__device__ float g_partial[NBLOCKS];

__device__ __forceinline__ uint64_t pk2(float lo, float hi) {
    uint64_t r;
    asm("mov.b64 %0, {%1, %2};" : "=l"(r) : "f"(lo), "f"(hi));
    return r;
}
__device__ __forceinline__ uint64_t fma_f32x2(uint64_t a, uint64_t b, uint64_t c) {
    uint64_t d;
    asm("fma.rn.f32x2 %0, %1, %2, %3;" : "=l"(d) : "l"(a), "l"(b), "l"(c));
    return d;
}
__device__ __forceinline__ float2 upk2(uint64_t v) {
    float2 r;
    asm("mov.b64 {%0, %1}, %2;" : "=f"(r.x), "=f"(r.y) : "l"(v));
    return r;
}

// One ref-pair body at immediate smem offset OFF (bytes) from 'addr'.
#define PAIR_BODY(OFF)                                                          \
    {                                                                           \
        uint64_t X, Y, Z, W;                                                    \
        asm volatile("ld.shared.v2.b64 {%0,%1}, [%2+" #OFF "];"                 \
                     : "=l"(X), "=l"(Y) : "r"(addr));                           \
        asm volatile("ld.shared.v2.b64 {%0,%1}, [%2+" #OFF "+16];"              \
                     : "=l"(Z), "=l"(W) : "r"(addr));                           \
        uint64_t ta = fma_f32x2(QXA, X, fma_f32x2(QYA, Y, fma_f32x2(QZA, Z, W)));\
        uint64_t tb = fma_f32x2(QXB, X, fma_f32x2(QYB, Y, fma_f32x2(QZB, Z, W)));\
        float2 fa = upk2(ta);                                                   \
        float2 fb = upk2(tb);                                                   \
        ma0 = fminf(ma0, fa.x);                                                 \
        ma1 = fminf(ma1, fa.y);                                                 \
        mb0 = fminf(mb0, fb.x);                                                 \
        mb1 = fminf(mb1, fb.y);                                                 \
    }

__global__ void __launch_bounds__(TPB, 1)
chamfer_min_kernel(const float* __restrict__ pc2,
                   const float* __restrict__ pc1w)
{
    extern __shared__ float4 s[];

    const int b  = blockIdx.x / QBLOCKS;
    const int qb = blockIdx.x % QBLOCKS;

    // Stage all ref points of this batch, pre-scaled and pair-packed.
    const float* __restrict__ rp = pc1w + (size_t)b * 3 * NPTS;
    for (int p = threadIdx.x; p < NPAIRS; p += TPB) {
        float x0 = rp[2 * p],            x1 = rp[2 * p + 1];
        float y0 = rp[NPTS + 2 * p],     y1 = rp[NPTS + 2 * p + 1];
        float z0 = rp[2 * NPTS + 2 * p], z1 = rp[2 * NPTS + 2 * p + 1];
        float w0 = fmaf(x0, x0, fmaf(y0, y0, z0 * z0));
        float w1 = fmaf(x1, x1, fmaf(y1, y1, z1 * z1));
        s[2 * p]     = make_float4(-2.0f * x0, -2.0f * x1, -2.0f * y0, -2.0f * y1);
        s[2 * p + 1] = make_float4(-2.0f * z0, -2.0f * z1, w0, w1);
    }
    __syncthreads();

    // Two query points per thread.
    const int na = qb * QPB + threadIdx.x;
    const int nb = na + TPB;
    const float* __restrict__ qp = pc2 + (size_t)b * 3 * NPTS;
    const float qxa = qp[na], qya = qp[NPTS + na], qza = qp[2 * NPTS + na];
    const float qxb = qp[nb], qyb = qp[NPTS + nb], qzb = qp[2 * NPTS + nb];
    const float q2a = fmaf(qxa, qxa, fmaf(qya, qya, qza * qza));
    const float q2b = fmaf(qxb, qxb, fmaf(qyb, qyb, qzb * qzb));

    const uint64_t QXA = pk2(qxa, qxa), QYA = pk2(qya, qya), QZA = pk2(qza, qza);
    const uint64_t QXB = pk2(qxb, qxb), QYB = pk2(qyb, qyb), QZB = pk2(qzb, qzb);

    float ma0 = 3.4e38f, ma1 = 3.4e38f;
    float mb0 = 3.4e38f, mb1 = 3.4e38f;

    uint32_t addr = (uint32_t)__cvta_generic_to_shared(s);

    // 8 ref-pairs (16 ref points) per outer iteration, immediate offsets.
    #pragma unroll 1
    for (int p = 0; p < NPAIRS; p += 8) {
        PAIR_BODY(0)
        PAIR_BODY(32)
        PAIR_BODY(64)
        PAIR_BODY(96)
        PAIR_BODY(128)
        PAIR_BODY(160)
        PAIR_BODY(192)
        PAIR_BODY(224)
        addr += 8 * 32;
    }

    float da = fmaxf(q2a + fminf(ma0, ma1), 0.0f);
    float db = fmaxf(q2b + fminf(mb0, mb1), 0.0f);

    // Deterministic block-level sum reduction.
    __shared__ float red[TPB];
    red[threadIdx.x] = da + db;
    __syncthreads();
    #pragma unroll
    for (int sH = TPB / 2; sH > 0; sH >>= 1) {
        if (threadIdx.x < sH) red[threadIdx.x] += red[threadIdx.x + sH];
        __syncthreads();
    }
    if (threadIdx.x == 0) g_partial[blockIdx.x] = red[0];
}

__global__ void chamfer_finalize_kernel(float* __restrict__ out)
{
    __shared__ float red[NBLOCKS];
    red[threadIdx.x] = g_partial[threadIdx.x];
    __syncthreads();
    #pragma unroll
    for (int sH = NBLOCKS / 2; sH > 0; sH >>= 1) {
        if (threadIdx.x < sH) red[threadIdx.x] += red[threadIdx.x + sH];
        __syncthreads();
    }
    if (threadIdx.x == 0) {
        out[0] = red[0] * (2.0f / (float)BATCH);  // 2 * mean over batches
    }
}

extern "C" void kernel_launch(void* const* d_in, const int* in_sizes, int n_in,
                              void* d_out, int out_size)
{
    const float* pc2  = (const float*)d_in[0];
    const float* pc1w = (const float*)d_in[1];
    float* out = (float*)d_out;

    cudaFuncSetAttribute(chamfer_min_kernel,
                         cudaFuncAttributeMaxDynamicSharedMemorySize,
                         SMEM_BYTES);

    chamfer_min_kernel<<<NBLOCKS, TPB, SMEM_BYTES>>>(pc2, pc1w);
    chamfer_finalize_kernel<<<1, NBLOCKS>>>(out);
}